// round 13
// baseline (speedup 1.0000x reference)
#include <cuda_runtime.h>
#include <cstdint>
#include <cstddef>

// Problem constants
#define NB    8
#define CTOT  64
#define GRP   8
#define CG    8
#define N_    64          // NB*GRP independent slices
#define NC    512         // N_*CG = global channel count
#define F_    256
#define T_    256
#define FT    65536
#define EPSV  1e-5f

// ---------------- scratch (device globals; no allocation allowed) -------------
__device__ float2 g_rowsum[NC][F_];                 // per (n,c): sum over t, for each f
__device__ __align__(16) float2 g_colsum2[2][NC][T_]; // per (n,c): partial col sums (2 f-halves)
__device__ float2 g_corner[NC][4];                  // (0,0),(0,T-1),(F-1,0),(F-1,T-1)
__device__ float2 g_wf[NC][F_];                     // gate over f (packed r/i)
__device__ __align__(16) float2 g_wt[NC][T_];       // gate over t
__device__ float2 g_a2[NC];                         // softmax weights from conv-branch mean
__device__ float2 g_weff[N_][CG * 9];               // per-n combined 3x3 kernel per input channel
__device__ float2 g_cb[N_];                         // sum_o a1[o]*b3[o]
__device__ float2 g_mu[NC];                         // mean of gated field y = x*wf*wt
__device__ float2 g_inv[NC];                        // rsqrt(var(y)+eps)

__device__ __forceinline__ float sigm(float z) { return 1.0f / (1.0f + __expf(-z)); }
__device__ __forceinline__ float2 f2add(float2 a, float2 b) { return make_float2(a.x + b.x, a.y + b.y); }

// ---------------- K1: row sums, col sums, corners (one pass over x) -----------
__global__ void k1_rowcol(const float2* __restrict__ x) {
    int nc = blockIdx.x >> 1, half = blockIdx.x & 1;
    const float2* img = x + (size_t)nc * FT;
    const float4* img4 = reinterpret_cast<const float4*>(img) + (size_t)half * 128 * 128;
    int tid = threadIdx.x;
    int w = tid >> 5, l = tid & 31;

    __shared__ float4 s_col[8][128];

    float4 colacc[4];
#pragma unroll
    for (int k = 0; k < 4; k++) colacc[k] = make_float4(0.f, 0.f, 0.f, 0.f);

    int fbase = w * 16;
#pragma unroll 2
    for (int fr = 0; fr < 16; fr++) {
        int f = fbase + fr;
        const float4* row = img4 + (size_t)f * 128;
        float4 v[4];
#pragma unroll
        for (int k = 0; k < 4; k++) v[k] = __ldcs(row + l + 32 * k);
        float pr = 0.f, pi = 0.f;
#pragma unroll
        for (int k = 0; k < 4; k++) {
            pr += v[k].x + v[k].z;
            pi += v[k].y + v[k].w;
            colacc[k].x += v[k].x; colacc[k].y += v[k].y;
            colacc[k].z += v[k].z; colacc[k].w += v[k].w;
        }
#pragma unroll
        for (int off = 16; off > 0; off >>= 1) {
            pr += __shfl_down_sync(0xffffffffu, pr, off);
            pi += __shfl_down_sync(0xffffffffu, pi, off);
        }
        if (l == 0) g_rowsum[nc][half * 128 + f] = make_float2(pr, pi);
    }
#pragma unroll
    for (int k = 0; k < 4; k++) s_col[w][l + 32 * k] = colacc[k];
    __syncthreads();
    if (tid < 128) {
        float4 s = make_float4(0.f, 0.f, 0.f, 0.f);
#pragma unroll
        for (int ww = 0; ww < 8; ww++) {
            float4 c = s_col[ww][tid];
            s.x += c.x; s.y += c.y; s.z += c.z; s.w += c.w;
        }
        reinterpret_cast<float4*>(&g_colsum2[half][nc][0])[tid] = s;
    }
    if (tid == 0) {
        if (half == 0) {
            g_corner[nc][0] = img[0];
            g_corner[nc][1] = img[T_ - 1];
        } else {
            g_corner[nc][2] = img[(size_t)(F_ - 1) * T_];
            g_corner[nc][3] = img[(size_t)(F_ - 1) * T_ + (T_ - 1)];
        }
    }
}

// ---------------- K2: gates wf/wt, a1, a2, Weff, cb (tiny, per n) -------------
__global__ void k2_gates(const float* __restrict__ w1r, const float* __restrict__ b1r,
                         const float* __restrict__ w1i, const float* __restrict__ b1i,
                         const float* __restrict__ w3r, const float* __restrict__ b3r,
                         const float* __restrict__ w3i, const float* __restrict__ b3i,
                         const float* __restrict__ gnb_r, const float* __restrict__ gnb_i) {
    int n = blockIdx.x;
    int tid = threadIdx.x;

    __shared__ float2 s_tot[8];
    __shared__ float2 s_S[8][9];
    __shared__ float2 s_a1[8];      // logits, then softmax values
    __shared__ float  s_lr[8], s_li[8];

    // phase 1: 1x1 conv on pooled means -> sigmoid gates
    for (int task = tid; task < 4096; task += blockDim.x) {
        int o = task & 7, s = task >> 3;
        float accr = b1r[o], acci = b1i[o];
        if (s < F_) {
#pragma unroll
            for (int c = 0; c < 8; c++) {
                float2 rs = g_rowsum[n * 8 + c][s];
                accr += w1r[o * 8 + c] * (rs.x * (1.f / (float)T_));
                acci += w1i[o * 8 + c] * (rs.y * (1.f / (float)T_));
            }
            float sr = sigm(accr), si = sigm(acci);
            g_wf[n * 8 + o][s] = make_float2(sr - si, si + sr);
        } else {
            int t = s - F_;
#pragma unroll
            for (int c = 0; c < 8; c++) {
                float2 c0 = g_colsum2[0][n * 8 + c][t];
                float2 c1 = g_colsum2[1][n * 8 + c][t];
                accr += w1r[o * 8 + c] * ((c0.x + c1.x) * (1.f / (float)F_));
                acci += w1i[o * 8 + c] * ((c0.y + c1.y) * (1.f / (float)F_));
            }
            float sr = sigm(accr), si = sigm(acci);
            g_wt[n * 8 + o][t] = make_float2(sr - si, si + sr);
        }
    }
    __syncthreads();

    // phase 2: per-channel totals (parallel: warp w reduces channel w)
    {
        int c = tid >> 5, lane = tid & 31;
        float tr = 0.f, ti = 0.f;
#pragma unroll
        for (int f = lane; f < F_; f += 32) {
            float2 r = g_rowsum[n * 8 + c][f];
            tr += r.x; ti += r.y;
        }
#pragma unroll
        for (int off = 16; off > 0; off >>= 1) {
            tr += __shfl_down_sync(0xffffffffu, tr, off);
            ti += __shfl_down_sync(0xffffffffu, ti, off);
        }
        if (lane == 0) s_tot[c] = make_float2(tr, ti);
    }
    __syncthreads();

    // phase 3: boundary-corrected shifted sums S[i][kh*3+kw]
    if (tid < 72) {
        int i = tid / 9, tap = tid % 9, kh = tap / 3, kw = tap % 3;
        float2 S = s_tot[i];
        if (kh == 0)      { float2 e = g_rowsum[n * 8 + i][F_ - 1]; S.x -= e.x; S.y -= e.y; }
        else if (kh == 2) { float2 e = g_rowsum[n * 8 + i][0];      S.x -= e.x; S.y -= e.y; }
        if (kw == 0) {
            float2 e0 = g_colsum2[0][n * 8 + i][T_ - 1], e1 = g_colsum2[1][n * 8 + i][T_ - 1];
            S.x -= e0.x + e1.x; S.y -= e0.y + e1.y;
        } else if (kw == 2) {
            float2 e0 = g_colsum2[0][n * 8 + i][0], e1 = g_colsum2[1][n * 8 + i][0];
            S.x -= e0.x + e1.x; S.y -= e0.y + e1.y;
        }
        int ci = -1;
        if (kh == 0 && kw == 0) ci = 3;
        if (kh == 0 && kw == 2) ci = 2;
        if (kh == 2 && kw == 0) ci = 1;
        if (kh == 2 && kw == 2) ci = 0;
        if (ci >= 0) { float2 co = g_corner[n * 8 + i][ci]; S.x += co.x; S.y += co.y; }
        s_S[i][tap] = S;
    }
    __syncthreads();

    // phase 4: logits of a2 = mean(conv(x)) + b3 ; a1 logits = gnb
    if (tid < 8) {
        int c = tid;
        float lr = 0.f, li = 0.f;
        for (int i = 0; i < 8; i++) {
#pragma unroll
            for (int tap = 0; tap < 9; tap++) {
                lr += w3r[(c * 8 + i) * 9 + tap] * s_S[i][tap].x;
                li += w3i[(c * 8 + i) * 9 + tap] * s_S[i][tap].y;
            }
        }
        s_lr[c] = lr * (1.f / (float)FT) + b3r[c];
        s_li[c] = li * (1.f / (float)FT) + b3i[c];
        s_a1[c] = make_float2(gnb_r[c], gnb_i[c]);
    }
    __syncthreads();

    // phase 5: softmaxes, cb
    if (tid == 0) {
        float mr = -1e30f, mi = -1e30f, m1r = -1e30f, m1i = -1e30f;
        for (int c = 0; c < 8; c++) {
            mr = fmaxf(mr, s_lr[c]); mi = fmaxf(mi, s_li[c]);
            m1r = fmaxf(m1r, s_a1[c].x); m1i = fmaxf(m1i, s_a1[c].y);
        }
        float er[8], ei[8], e1r[8], e1i[8];
        float zr = 0.f, zi = 0.f, z1r = 0.f, z1i = 0.f;
        for (int c = 0; c < 8; c++) {
            er[c]  = expf(s_lr[c] - mr);       zr  += er[c];
            ei[c]  = expf(s_li[c] - mi);       zi  += ei[c];
            e1r[c] = expf(s_a1[c].x - m1r);    z1r += e1r[c];
            e1i[c] = expf(s_a1[c].y - m1i);    z1i += e1i[c];
        }
        float cbr = 0.f, cbi = 0.f;
        for (int c = 0; c < 8; c++) {
            g_a2[n * 8 + c] = make_float2(er[c] / zr, ei[c] / zi);
            float a1r = e1r[c] / z1r, a1ic = e1i[c] / z1i;
            s_a1[c] = make_float2(a1r, a1ic);
            cbr += a1r * b3r[c]; cbi += a1ic * b3i[c];
        }
        g_cb[n] = make_float2(cbr, cbi);
    }
    __syncthreads();

    // phase 6: effective single-output conv kernel
    if (tid < 72) {
        int i = tid / 9, tap = tid % 9;
        float wr = 0.f, wi = 0.f;
#pragma unroll
        for (int o = 0; o < 8; o++) {
            wr += s_a1[o].x * w3r[(o * 8 + i) * 9 + tap];
            wi += s_a1[o].y * w3i[(o * 8 + i) * 9 + tap];
        }
        g_weff[n][i * 9 + tap] = make_float2(wr, wi);
    }
}

// ---------------- K3: mean/var of gated field y = x*wf[f]*wt[t] ---------------
__global__ void k3_stats(const float2* __restrict__ x) {
    int nc = blockIdx.x;
    int tid = threadIdx.x;
    int j = tid & 127, half = tid >> 7;
    __shared__ float2 s_wfa[256];
    __shared__ float  s4[8][4];

    s_wfa[tid] = g_wf[nc][tid];
    float4 wtp = reinterpret_cast<const float4*>(&g_wt[nc][0])[j];  // wt[2j], wt[2j+1]
    __syncthreads();

    const float4* img4 = reinterpret_cast<const float4*>(x + (size_t)nc * FT);

    float sr = 0.f, si = 0.f, qr = 0.f, qi = 0.f;
#pragma unroll 8
    for (int it = 0; it < 128; it++) {
        int row = 2 * it + half;
        float4 v = __ldcs(img4 + (size_t)row * 128 + j);
        float2 wf = s_wfa[row];
        float yr0 = v.x * wf.x * wtp.x;
        float yi0 = v.y * wf.y * wtp.y;
        float yr1 = v.z * wf.x * wtp.z;
        float yi1 = v.w * wf.y * wtp.w;
        sr += yr0 + yr1; qr += yr0 * yr0 + yr1 * yr1;
        si += yi0 + yi1; qi += yi0 * yi0 + yi1 * yi1;
    }
    int l = tid & 31, w = tid >> 5;
#pragma unroll
    for (int off = 16; off > 0; off >>= 1) {
        sr += __shfl_down_sync(0xffffffffu, sr, off);
        si += __shfl_down_sync(0xffffffffu, si, off);
        qr += __shfl_down_sync(0xffffffffu, qr, off);
        qi += __shfl_down_sync(0xffffffffu, qi, off);
    }
    if (l == 0) { s4[w][0] = sr; s4[w][1] = si; s4[w][2] = qr; s4[w][3] = qi; }
    __syncthreads();
    if (tid == 0) {
        float tsr = 0.f, tsi = 0.f, tqr = 0.f, tqi = 0.f;
#pragma unroll
        for (int ww = 0; ww < 8; ww++) { tsr += s4[ww][0]; tsi += s4[ww][1]; tqr += s4[ww][2]; tqi += s4[ww][3]; }
        float mur = tsr * (1.f / (float)FT), mui = tsi * (1.f / (float)FT);
        float vr = tqr * (1.f / (float)FT) - mur * mur;
        float vi = tqi * (1.f / (float)FT) - mui * mui;
        g_mu[nc]  = make_float2(mur, mui);
        g_inv[nc] = make_float2(rsqrtf(vr + EPSV), rsqrtf(vi + EPSV));
    }
}

// ---------------- K4: column-pair vectorized streaming attention --------------
// r11 structure (prefetch, static 3x6 unroll, shfl halo, no in-loop barriers),
// but each thread owns TWO adjacent columns via float4 loads/stores:
//  - the 40 loop-invariant weff LDS.128 per thread-row now serve 2 columns
//  - LDG/STG instruction count per byte halves (same bytes, 128-bit ops)
//  - pair-interior horizontal taps are in-register; shfl per column halves
// Warp covers 64 loaded / 60 output columns (2-col halo keeps 16B alignment).
#define FSEG 16
#define K4_THREADS 160   // 5 warps x 60 output cols = 300 >= 256

// Row r's contribution for both columns of the pair.
// A/B/C[kw] hold (col0.r, col0.i, col1.r, col1.i) partials for kh=2/1/0.
__device__ __forceinline__ void accum_row_v(const float4 v[8], const float4* wef,
                                            float4 A[3], float4 B[3], float4 C[3]) {
#pragma unroll
    for (int c = 0; c < 8; c++) {
        float4 vc = v[c];
        float4 a = wef[c * 6 + 0];   // taps 0,1   (kh0: kw0,kw1)
        float4 b = wef[c * 6 + 1];   // taps 2,3   (kh0:kw2, kh1:kw0)
        float4 d = wef[c * 6 + 2];   // taps 4,5   (kh1: kw1,kw2)
        float4 e = wef[c * 6 + 3];   // taps 6,7   (kh2: kw0,kw1)
        float4 f = wef[c * 6 + 4];   // tap 8 .xy  (kh2: kw2)
        C[0].x = fmaf(a.x, vc.x, C[0].x); C[0].y = fmaf(a.y, vc.y, C[0].y);
        C[0].z = fmaf(a.x, vc.z, C[0].z); C[0].w = fmaf(a.y, vc.w, C[0].w);
        C[1].x = fmaf(a.z, vc.x, C[1].x); C[1].y = fmaf(a.w, vc.y, C[1].y);
        C[1].z = fmaf(a.z, vc.z, C[1].z); C[1].w = fmaf(a.w, vc.w, C[1].w);
        C[2].x = fmaf(b.x, vc.x, C[2].x); C[2].y = fmaf(b.y, vc.y, C[2].y);
        C[2].z = fmaf(b.x, vc.z, C[2].z); C[2].w = fmaf(b.y, vc.w, C[2].w);
        B[0].x = fmaf(b.z, vc.x, B[0].x); B[0].y = fmaf(b.w, vc.y, B[0].y);
        B[0].z = fmaf(b.z, vc.z, B[0].z); B[0].w = fmaf(b.w, vc.w, B[0].w);
        B[1].x = fmaf(d.x, vc.x, B[1].x); B[1].y = fmaf(d.y, vc.y, B[1].y);
        B[1].z = fmaf(d.x, vc.z, B[1].z); B[1].w = fmaf(d.y, vc.w, B[1].w);
        B[2].x = fmaf(d.z, vc.x, B[2].x); B[2].y = fmaf(d.w, vc.y, B[2].y);
        B[2].z = fmaf(d.z, vc.z, B[2].z); B[2].w = fmaf(d.w, vc.w, B[2].w);
        A[0].x = fmaf(e.x, vc.x, A[0].x); A[0].y = fmaf(e.y, vc.y, A[0].y);
        A[0].z = fmaf(e.x, vc.z, A[0].z); A[0].w = fmaf(e.y, vc.w, A[0].w);
        A[1].x = fmaf(e.z, vc.x, A[1].x); A[1].y = fmaf(e.w, vc.y, A[1].y);
        A[1].z = fmaf(e.z, vc.z, A[1].z); A[1].w = fmaf(e.w, vc.w, A[1].w);
        A[2].x = fmaf(f.x, vc.x, A[2].x); A[2].y = fmaf(f.y, vc.y, A[2].y);
        A[2].z = fmaf(f.x, vc.z, A[2].z); A[2].w = fmaf(f.y, vc.w, A[2].w);
    }
}

__global__ __launch_bounds__(K4_THREADS, 3) void k4_vec(const float2* __restrict__ x, float2* __restrict__ out,
                                                        const float* __restrict__ gnw_r, const float* __restrict__ gnb_r,
                                                        const float* __restrict__ gnw_i, const float* __restrict__ gnb_i) {
    int n = blockIdx.y;
    int F0 = blockIdx.x * FSEG;
    int tid = threadIdx.x, w = tid >> 5, l = tid & 31;
    int tp = w * 60 + 2 * l - 2;                  // first column of this lane's pair (even)
    bool tin  = ((unsigned)tp < (unsigned)T_);    // tp in [0,254] -> pair fully inside
    bool tout = (l >= 1) && (l <= 30) && tin;

    __shared__ float2 s_weff[8][12];              // 9 taps + pad -> float4-readable (6 float4/ch)
    __shared__ float2 s_awf[8][FSEG];
    __shared__ __align__(16) float2 s_wt[8][T_];
    __shared__ float2 s_alpha[8], s_cp[8];
    __shared__ float2 s_base;

    if (tid < 72) s_weff[tid / 9][tid % 9] = g_weff[n][tid];
    if (tid < 8) {
        int i = tid;
        float2 a2 = g_a2[n * 8 + i], inv = g_inv[n * 8 + i], mu = g_mu[n * 8 + i];
        s_alpha[i] = make_float2(a2.x * gnw_r[i] * inv.x, a2.y * gnw_i[i] * inv.y);
        s_cp[i]    = make_float2(a2.x * (gnb_r[i] - gnw_r[i] * inv.x * mu.x),
                                 a2.y * (gnb_i[i] - gnw_i[i] * inv.y * mu.y));
    }
    for (int idx = tid; idx < 2048; idx += K4_THREADS)
        s_wt[idx >> 8][idx & 255] = g_wt[n * 8 + (idx >> 8)][idx & 255];
    __syncthreads();
    if (tid < 8 * FSEG) {
        int c = tid >> 4, m = tid & (FSEG - 1);   // FSEG == 16
        float2 wf = g_wf[n * 8 + c][F0 + m], al = s_alpha[c];
        s_awf[c][m] = make_float2(al.x * wf.x, al.y * wf.y);
    }
    if (tid == 0) {
        float2 b = g_cb[n];
#pragma unroll
        for (int c = 0; c < 8; c++) b = f2add(b, s_cp[c]);
        s_base = b;
    }
    __syncthreads();

    const float4* wef = reinterpret_cast<const float4*>(&s_weff[0][0]);
    int tpc = tin ? tp : 0;
    // float4 view: element index = c*(FT/2) + r*(T_/2) + tp/2
    const float4* xq4 = reinterpret_cast<const float4*>(x + (size_t)(n * 8) * FT) + (tpc >> 1);
    float4* oq4 = reinterpret_cast<float4*>(out + (size_t)(n * 8) * FT) + (tpc >> 1);

    float4 v[2][8];          // double-buffered current/next row (period 2)
    float4 acc[3][3];        // acc[slot][kw] ring accumulators (period 3), both cols
#pragma unroll
    for (int s0 = 0; s0 < 3; s0++)
#pragma unroll
        for (int kw = 0; kw < 3; kw++) acc[s0][kw] = make_float4(0.f, 0.f, 0.f, 0.f);

    {   // preamble: row F0-1 into v[0]
        int r0 = F0 - 1;
        bool ok0 = tin && (r0 >= 0);
#pragma unroll
        for (int c = 0; c < 8; c++)
            v[0][c] = ok0 ? xq4[(size_t)c * (FT / 2) + (size_t)r0 * (T_ / 2)]
                          : make_float4(0.f, 0.f, 0.f, 0.f);
    }

    // 18 row-iterations = 3 macro x 6 steps; all ring-slot / buffer indices
    // are compile-time constants inside the 6-step unroll.
#pragma unroll 1
    for (int mi = 0; mi < 3; mi++) {
#pragma unroll
        for (int s = 0; s < 6; s++) {
            int rr = mi * 6 + s;
            int r = F0 - 1 + rr;
            int cur = s & 1, nxt = cur ^ 1;

            // prefetch next row into the other buffer
            int rn = r + 1;
            bool okn = tin && (rn < F_) && (rn <= F0 + FSEG);
#pragma unroll
            for (int c = 0; c < 8; c++)
                v[nxt][c] = okn ? xq4[(size_t)c * (FT / 2) + (size_t)rn * (T_ / 2)]
                                : make_float4(0.f, 0.f, 0.f, 0.f);

            // accumulate row r: A = row r-1 (kh2), B = row r (kh1), C = row r+1 (kh0)
            accum_row_v(v[cur], wef, acc[s % 3], acc[(s + 1) % 3], acc[(s + 2) % 3]);

            if (rr >= 2) {
                // output row m = r-1 from slot A = acc[s%3]
                // col0: S = B0(tp-1)[shfl-up of neighbor col1] + B1(col0) + B2(col1)
                // col1: S = B0(col0) + B1(col1) + B2(tp+2)[shfl-down of neighbor col0]
                float upz = __shfl_up_sync(0xffffffffu, acc[s % 3][0].z, 1);
                float upw = __shfl_up_sync(0xffffffffu, acc[s % 3][0].w, 1);
                float dnx = __shfl_down_sync(0xffffffffu, acc[s % 3][2].x, 1);
                float dny = __shfl_down_sync(0xffffffffu, acc[s % 3][2].y, 1);
                if (tout) {
                    int m = r - 1;
                    float2 wv0 = make_float2(s_base.x + upz + acc[s % 3][1].x + acc[s % 3][2].z,
                                             s_base.y + upw + acc[s % 3][1].y + acc[s % 3][2].w);
                    float2 wv1 = make_float2(s_base.x + acc[s % 3][0].x + acc[s % 3][1].z + dnx,
                                             s_base.y + acc[s % 3][0].y + acc[s % 3][1].w + dny);
                    // reload row m (L1 hit: fetched 2 iterations ago, default caching)
                    float4 pv[8];
#pragma unroll
                    for (int c = 0; c < 8; c++)
                        pv[c] = xq4[(size_t)c * (FT / 2) + (size_t)m * (T_ / 2)];
#pragma unroll
                    for (int c = 0; c < 8; c++) {
                        float2 g = s_awf[c][m - F0];
                        float4 wt4 = reinterpret_cast<const float4*>(&s_wt[c][0])[tp >> 1];
                        wv0.x = fmaf(g.x * wt4.x, pv[c].x, wv0.x);
                        wv0.y = fmaf(g.y * wt4.y, pv[c].y, wv0.y);
                        wv1.x = fmaf(g.x * wt4.z, pv[c].z, wv1.x);
                        wv1.y = fmaf(g.y * wt4.w, pv[c].w, wv1.y);
                    }
                    float s0r = sigm(wv0.x), s0i = sigm(wv0.y);
                    float s1r = sigm(wv1.x), s1i = sigm(wv1.y);
#pragma unroll
                    for (int c = 0; c < 8; c++)
                        __stcs(oq4 + (size_t)c * (FT / 2) + (size_t)m * (T_ / 2),
                               make_float4(pv[c].x * s0r, pv[c].y * s0i,
                                           pv[c].z * s1r, pv[c].w * s1i));
                }
            }

            // clear retired slot A — it is reused as slot C two steps later
#pragma unroll
            for (int kw = 0; kw < 3; kw++) acc[s % 3][kw] = make_float4(0.f, 0.f, 0.f, 0.f);
        }
    }
}

// ------------------------------- launcher ------------------------------------
extern "C" void kernel_launch(void* const* d_in, const int* in_sizes, int n_in,
                              void* d_out, int out_size) {
    const float2* x    = (const float2*)d_in[0];
    const float* w1r   = (const float*)d_in[1];
    const float* b1r   = (const float*)d_in[2];
    const float* w1i   = (const float*)d_in[3];
    const float* b1i   = (const float*)d_in[4];
    const float* w3r   = (const float*)d_in[5];
    const float* b3r   = (const float*)d_in[6];
    const float* w3i   = (const float*)d_in[7];
    const float* b3i   = (const float*)d_in[8];
    const float* gnw_r = (const float*)d_in[9];
    const float* gnb_r = (const float*)d_in[10];
    const float* gnw_i = (const float*)d_in[11];
    const float* gnb_i = (const float*)d_in[12];
    float2* out = (float2*)d_out;

    k1_rowcol<<<NC * 2, 256>>>(x);
    k2_gates<<<N_, 256>>>(w1r, b1r, w1i, b1i, w3r, b3r, w3i, b3i, gnb_r, gnb_i);
    k3_stats<<<NC, 256>>>(x);
    dim3 g4(F_ / FSEG, N_);
    k4_vec<<<g4, K4_THREADS>>>(x, out, gnw_r, gnb_r, gnw_i, gnb_i);
}

// round 14
// speedup vs baseline: 1.0963x; 1.0963x over previous
#include <cuda_runtime.h>
#include <cstdint>
#include <cstddef>

// Problem constants
#define NB    8
#define CTOT  64
#define GRP   8
#define CG    8
#define N_    64          // NB*GRP independent slices
#define NC    512         // N_*CG = global channel count
#define F_    256
#define T_    256
#define FT    65536
#define EPSV  1e-5f

// ---------------- scratch (device globals; no allocation allowed) -------------
__device__ float2 g_rowsum[NC][F_];                 // per (n,c): sum over t, for each f
__device__ __align__(16) float2 g_colsum2[2][NC][T_]; // per (n,c): partial col sums (2 f-halves)
__device__ float2 g_corner[NC][4];                  // (0,0),(0,T-1),(F-1,0),(F-1,T-1)
__device__ float2 g_wf[NC][F_];                     // gate over f (packed r/i)
__device__ __align__(16) float2 g_wt[NC][T_];       // gate over t
__device__ float2 g_a2[NC];                         // softmax weights from conv-branch mean
__device__ float2 g_weff[N_][CG * 9];               // per-n combined 3x3 kernel per input channel
__device__ float2 g_cb[N_];                         // sum_o a1[o]*b3[o]
__device__ float2 g_mu[NC];                         // mean of gated field y = x*wf*wt
__device__ float2 g_inv[NC];                        // rsqrt(var(y)+eps)

__device__ __forceinline__ float sigm(float z) { return 1.0f / (1.0f + __expf(-z)); }
__device__ __forceinline__ float2 f2add(float2 a, float2 b) { return make_float2(a.x + b.x, a.y + b.y); }

// ---------------- K1: row sums, col sums, corners (one pass over x) -----------
__global__ void k1_rowcol(const float2* __restrict__ x) {
    int nc = blockIdx.x >> 1, half = blockIdx.x & 1;
    const float2* img = x + (size_t)nc * FT;
    const float4* img4 = reinterpret_cast<const float4*>(img) + (size_t)half * 128 * 128;
    int tid = threadIdx.x;
    int w = tid >> 5, l = tid & 31;

    __shared__ float4 s_col[8][128];

    float4 colacc[4];
#pragma unroll
    for (int k = 0; k < 4; k++) colacc[k] = make_float4(0.f, 0.f, 0.f, 0.f);

    int fbase = w * 16;
#pragma unroll 2
    for (int fr = 0; fr < 16; fr++) {
        int f = fbase + fr;
        const float4* row = img4 + (size_t)f * 128;
        float4 v[4];
#pragma unroll
        for (int k = 0; k < 4; k++) v[k] = __ldcs(row + l + 32 * k);
        float pr = 0.f, pi = 0.f;
#pragma unroll
        for (int k = 0; k < 4; k++) {
            pr += v[k].x + v[k].z;
            pi += v[k].y + v[k].w;
            colacc[k].x += v[k].x; colacc[k].y += v[k].y;
            colacc[k].z += v[k].z; colacc[k].w += v[k].w;
        }
#pragma unroll
        for (int off = 16; off > 0; off >>= 1) {
            pr += __shfl_down_sync(0xffffffffu, pr, off);
            pi += __shfl_down_sync(0xffffffffu, pi, off);
        }
        if (l == 0) g_rowsum[nc][half * 128 + f] = make_float2(pr, pi);
    }
#pragma unroll
    for (int k = 0; k < 4; k++) s_col[w][l + 32 * k] = colacc[k];
    __syncthreads();
    if (tid < 128) {
        float4 s = make_float4(0.f, 0.f, 0.f, 0.f);
#pragma unroll
        for (int ww = 0; ww < 8; ww++) {
            float4 c = s_col[ww][tid];
            s.x += c.x; s.y += c.y; s.z += c.z; s.w += c.w;
        }
        reinterpret_cast<float4*>(&g_colsum2[half][nc][0])[tid] = s;
    }
    if (tid == 0) {
        if (half == 0) {
            g_corner[nc][0] = img[0];
            g_corner[nc][1] = img[T_ - 1];
        } else {
            g_corner[nc][2] = img[(size_t)(F_ - 1) * T_];
            g_corner[nc][3] = img[(size_t)(F_ - 1) * T_ + (T_ - 1)];
        }
    }
}

// ---------------- K2: gates wf/wt, a1, a2, Weff, cb (tiny, per n) -------------
__global__ void k2_gates(const float* __restrict__ w1r, const float* __restrict__ b1r,
                         const float* __restrict__ w1i, const float* __restrict__ b1i,
                         const float* __restrict__ w3r, const float* __restrict__ b3r,
                         const float* __restrict__ w3i, const float* __restrict__ b3i,
                         const float* __restrict__ gnb_r, const float* __restrict__ gnb_i) {
    int n = blockIdx.x;
    int tid = threadIdx.x;

    __shared__ float2 s_tot[8];
    __shared__ float2 s_S[8][9];
    __shared__ float2 s_a1[8];      // logits, then softmax values
    __shared__ float  s_lr[8], s_li[8];

    // phase 1: 1x1 conv on pooled means -> sigmoid gates
    for (int task = tid; task < 4096; task += blockDim.x) {
        int o = task & 7, s = task >> 3;
        float accr = b1r[o], acci = b1i[o];
        if (s < F_) {
#pragma unroll
            for (int c = 0; c < 8; c++) {
                float2 rs = g_rowsum[n * 8 + c][s];
                accr += w1r[o * 8 + c] * (rs.x * (1.f / (float)T_));
                acci += w1i[o * 8 + c] * (rs.y * (1.f / (float)T_));
            }
            float sr = sigm(accr), si = sigm(acci);
            g_wf[n * 8 + o][s] = make_float2(sr - si, si + sr);
        } else {
            int t = s - F_;
#pragma unroll
            for (int c = 0; c < 8; c++) {
                float2 c0 = g_colsum2[0][n * 8 + c][t];
                float2 c1 = g_colsum2[1][n * 8 + c][t];
                accr += w1r[o * 8 + c] * ((c0.x + c1.x) * (1.f / (float)F_));
                acci += w1i[o * 8 + c] * ((c0.y + c1.y) * (1.f / (float)F_));
            }
            float sr = sigm(accr), si = sigm(acci);
            g_wt[n * 8 + o][t] = make_float2(sr - si, si + sr);
        }
    }
    __syncthreads();

    // phase 2: per-channel totals (parallel: warp w reduces channel w)
    {
        int c = tid >> 5, lane = tid & 31;
        float tr = 0.f, ti = 0.f;
#pragma unroll
        for (int f = lane; f < F_; f += 32) {
            float2 r = g_rowsum[n * 8 + c][f];
            tr += r.x; ti += r.y;
        }
#pragma unroll
        for (int off = 16; off > 0; off >>= 1) {
            tr += __shfl_down_sync(0xffffffffu, tr, off);
            ti += __shfl_down_sync(0xffffffffu, ti, off);
        }
        if (lane == 0) s_tot[c] = make_float2(tr, ti);
    }
    __syncthreads();

    // phase 3: boundary-corrected shifted sums S[i][kh*3+kw]
    if (tid < 72) {
        int i = tid / 9, tap = tid % 9, kh = tap / 3, kw = tap % 3;
        float2 S = s_tot[i];
        if (kh == 0)      { float2 e = g_rowsum[n * 8 + i][F_ - 1]; S.x -= e.x; S.y -= e.y; }
        else if (kh == 2) { float2 e = g_rowsum[n * 8 + i][0];      S.x -= e.x; S.y -= e.y; }
        if (kw == 0) {
            float2 e0 = g_colsum2[0][n * 8 + i][T_ - 1], e1 = g_colsum2[1][n * 8 + i][T_ - 1];
            S.x -= e0.x + e1.x; S.y -= e0.y + e1.y;
        } else if (kw == 2) {
            float2 e0 = g_colsum2[0][n * 8 + i][0], e1 = g_colsum2[1][n * 8 + i][0];
            S.x -= e0.x + e1.x; S.y -= e0.y + e1.y;
        }
        int ci = -1;
        if (kh == 0 && kw == 0) ci = 3;
        if (kh == 0 && kw == 2) ci = 2;
        if (kh == 2 && kw == 0) ci = 1;
        if (kh == 2 && kw == 2) ci = 0;
        if (ci >= 0) { float2 co = g_corner[n * 8 + i][ci]; S.x += co.x; S.y += co.y; }
        s_S[i][tap] = S;
    }
    __syncthreads();

    // phase 4: logits of a2 = mean(conv(x)) + b3 ; a1 logits = gnb
    if (tid < 8) {
        int c = tid;
        float lr = 0.f, li = 0.f;
        for (int i = 0; i < 8; i++) {
#pragma unroll
            for (int tap = 0; tap < 9; tap++) {
                lr += w3r[(c * 8 + i) * 9 + tap] * s_S[i][tap].x;
                li += w3i[(c * 8 + i) * 9 + tap] * s_S[i][tap].y;
            }
        }
        s_lr[c] = lr * (1.f / (float)FT) + b3r[c];
        s_li[c] = li * (1.f / (float)FT) + b3i[c];
        s_a1[c] = make_float2(gnb_r[c], gnb_i[c]);
    }
    __syncthreads();

    // phase 5: softmaxes, cb
    if (tid == 0) {
        float mr = -1e30f, mi = -1e30f, m1r = -1e30f, m1i = -1e30f;
        for (int c = 0; c < 8; c++) {
            mr = fmaxf(mr, s_lr[c]); mi = fmaxf(mi, s_li[c]);
            m1r = fmaxf(m1r, s_a1[c].x); m1i = fmaxf(m1i, s_a1[c].y);
        }
        float er[8], ei[8], e1r[8], e1i[8];
        float zr = 0.f, zi = 0.f, z1r = 0.f, z1i = 0.f;
        for (int c = 0; c < 8; c++) {
            er[c]  = expf(s_lr[c] - mr);       zr  += er[c];
            ei[c]  = expf(s_li[c] - mi);       zi  += ei[c];
            e1r[c] = expf(s_a1[c].x - m1r);    z1r += e1r[c];
            e1i[c] = expf(s_a1[c].y - m1i);    z1i += e1i[c];
        }
        float cbr = 0.f, cbi = 0.f;
        for (int c = 0; c < 8; c++) {
            g_a2[n * 8 + c] = make_float2(er[c] / zr, ei[c] / zi);
            float a1r = e1r[c] / z1r, a1ic = e1i[c] / z1i;
            s_a1[c] = make_float2(a1r, a1ic);
            cbr += a1r * b3r[c]; cbi += a1ic * b3i[c];
        }
        g_cb[n] = make_float2(cbr, cbi);
    }
    __syncthreads();

    // phase 6: effective single-output conv kernel
    if (tid < 72) {
        int i = tid / 9, tap = tid % 9;
        float wr = 0.f, wi = 0.f;
#pragma unroll
        for (int o = 0; o < 8; o++) {
            wr += s_a1[o].x * w3r[(o * 8 + i) * 9 + tap];
            wi += s_a1[o].y * w3i[(o * 8 + i) * 9 + tap];
        }
        g_weff[n][i * 9 + tap] = make_float2(wr, wi);
    }
}

// ---------------- K3: mean/var of gated field y = x*wf[f]*wt[t] ---------------
__global__ void k3_stats(const float2* __restrict__ x) {
    int nc = blockIdx.x;
    int tid = threadIdx.x;
    int j = tid & 127, half = tid >> 7;
    __shared__ float2 s_wfa[256];
    __shared__ float  s4[8][4];

    s_wfa[tid] = g_wf[nc][tid];
    float4 wtp = reinterpret_cast<const float4*>(&g_wt[nc][0])[j];  // wt[2j], wt[2j+1]
    __syncthreads();

    const float4* img4 = reinterpret_cast<const float4*>(x + (size_t)nc * FT);

    float sr = 0.f, si = 0.f, qr = 0.f, qi = 0.f;
#pragma unroll 8
    for (int it = 0; it < 128; it++) {
        int row = 2 * it + half;
        float4 v = __ldcs(img4 + (size_t)row * 128 + j);
        float2 wf = s_wfa[row];
        float yr0 = v.x * wf.x * wtp.x;
        float yi0 = v.y * wf.y * wtp.y;
        float yr1 = v.z * wf.x * wtp.z;
        float yi1 = v.w * wf.y * wtp.w;
        sr += yr0 + yr1; qr += yr0 * yr0 + yr1 * yr1;
        si += yi0 + yi1; qi += yi0 * yi0 + yi1 * yi1;
    }
    int l = tid & 31, w = tid >> 5;
#pragma unroll
    for (int off = 16; off > 0; off >>= 1) {
        sr += __shfl_down_sync(0xffffffffu, sr, off);
        si += __shfl_down_sync(0xffffffffu, si, off);
        qr += __shfl_down_sync(0xffffffffu, qr, off);
        qi += __shfl_down_sync(0xffffffffu, qi, off);
    }
    if (l == 0) { s4[w][0] = sr; s4[w][1] = si; s4[w][2] = qr; s4[w][3] = qi; }
    __syncthreads();
    if (tid == 0) {
        float tsr = 0.f, tsi = 0.f, tqr = 0.f, tqi = 0.f;
#pragma unroll
        for (int ww = 0; ww < 8; ww++) { tsr += s4[ww][0]; tsi += s4[ww][1]; tqr += s4[ww][2]; tqi += s4[ww][3]; }
        float mur = tsr * (1.f / (float)FT), mui = tsi * (1.f / (float)FT);
        float vr = tqr * (1.f / (float)FT) - mur * mur;
        float vi = tqi * (1.f / (float)FT) - mui * mui;
        g_mu[nc]  = make_float2(mur, mui);
        g_inv[nc] = make_float2(rsqrtf(vr + EPSV), rsqrtf(vi + EPSV));
    }
}

// ---------------- K4: warp-autonomous streaming attention + gating ------------
// Round-11 kernel verbatim (measured best: 125.95us). Halo lanes, shfl-only
// exchange, software prefetch, pv reload from L1, FSEG=16, 3 CTAs, static
// 3x6 unroll with compile-time ring/buffer indices.
#define FSEG 16
#define K4_THREADS 288   // 9 warps x 30 output cols = 270 >= 256 (+ halo coverage)

// Row r's contribution: A += W[kh=2]*v (row r-1), B += W[kh=1]*v (row r), C += W[kh=0]*v (row r+1)
__device__ __forceinline__ void accum_row(const float2 v[8], const float4* wef,
                                          float2 A[3], float2 B[3], float2 C[3]) {
#pragma unroll
    for (int c = 0; c < 8; c++) {
        float2 vc = v[c];
        float4 a = wef[c * 6 + 0];   // taps 0,1   (kh0: kw0,kw1)
        float4 b = wef[c * 6 + 1];   // taps 2,3   (kh0:kw2, kh1:kw0)
        float4 d = wef[c * 6 + 2];   // taps 4,5   (kh1: kw1,kw2)
        float4 e = wef[c * 6 + 3];   // taps 6,7   (kh2: kw0,kw1)
        float4 f = wef[c * 6 + 4];   // tap 8 .xy  (kh2: kw2)
        C[0].x = fmaf(a.x, vc.x, C[0].x); C[0].y = fmaf(a.y, vc.y, C[0].y);
        C[1].x = fmaf(a.z, vc.x, C[1].x); C[1].y = fmaf(a.w, vc.y, C[1].y);
        C[2].x = fmaf(b.x, vc.x, C[2].x); C[2].y = fmaf(b.y, vc.y, C[2].y);
        B[0].x = fmaf(b.z, vc.x, B[0].x); B[0].y = fmaf(b.w, vc.y, B[0].y);
        B[1].x = fmaf(d.x, vc.x, B[1].x); B[1].y = fmaf(d.y, vc.y, B[1].y);
        B[2].x = fmaf(d.z, vc.x, B[2].x); B[2].y = fmaf(d.w, vc.y, B[2].y);
        A[0].x = fmaf(e.x, vc.x, A[0].x); A[0].y = fmaf(e.y, vc.y, A[0].y);
        A[1].x = fmaf(e.z, vc.x, A[1].x); A[1].y = fmaf(e.w, vc.y, A[1].y);
        A[2].x = fmaf(f.x, vc.x, A[2].x); A[2].y = fmaf(f.y, vc.y, A[2].y);
    }
}

__global__ __launch_bounds__(K4_THREADS, 3) void k4_warp(const float2* __restrict__ x, float2* __restrict__ out,
                                                         const float* __restrict__ gnw_r, const float* __restrict__ gnb_r,
                                                         const float* __restrict__ gnw_i, const float* __restrict__ gnb_i) {
    int n = blockIdx.y;
    int F0 = blockIdx.x * FSEG;
    int tid = threadIdx.x, w = tid >> 5, l = tid & 31;
    int t = w * 30 + l - 1;                       // column tracked by this lane (may be -1..270)
    bool tin  = ((unsigned)t < (unsigned)T_);
    bool tout = (l >= 1) && (l <= 30) && (t < T_);

    __shared__ float2 s_weff[8][12];              // 9 taps + pad -> float4-readable (6 float4/ch)
    __shared__ float2 s_awf[8][FSEG];
    __shared__ float2 s_wt[8][T_];
    __shared__ float2 s_alpha[8], s_cp[8];
    __shared__ float2 s_base;

    if (tid < 72) s_weff[tid / 9][tid % 9] = g_weff[n][tid];
    if (tid < 8) {
        int i = tid;
        float2 a2 = g_a2[n * 8 + i], inv = g_inv[n * 8 + i], mu = g_mu[n * 8 + i];
        s_alpha[i] = make_float2(a2.x * gnw_r[i] * inv.x, a2.y * gnw_i[i] * inv.y);
        s_cp[i]    = make_float2(a2.x * (gnb_r[i] - gnw_r[i] * inv.x * mu.x),
                                 a2.y * (gnb_i[i] - gnw_i[i] * inv.y * mu.y));
    }
    for (int idx = tid; idx < 2048; idx += K4_THREADS)
        s_wt[idx >> 8][idx & 255] = g_wt[n * 8 + (idx >> 8)][idx & 255];
    __syncthreads();
    if (tid < 8 * FSEG) {
        int c = tid >> 4, m = tid & (FSEG - 1);   // FSEG == 16
        float2 wf = g_wf[n * 8 + c][F0 + m], al = s_alpha[c];
        s_awf[c][m] = make_float2(al.x * wf.x, al.y * wf.y);
    }
    if (tid == 0) {
        float2 b = g_cb[n];
#pragma unroll
        for (int c = 0; c < 8; c++) b = f2add(b, s_cp[c]);
        s_base = b;
    }
    __syncthreads();

    const float4* wef = reinterpret_cast<const float4*>(&s_weff[0][0]);
    int tc = tin ? t : 0;
    const float2* xp = x + (size_t)(n * 8) * FT + tc;
    float2* op = out + (size_t)(n * 8) * FT + tc;

    float2 v[2][8];          // double-buffered current/next row (period 2)
    float2 acc[3][3];        // acc[slot][kw] ring accumulators (period 3)
#pragma unroll
    for (int s0 = 0; s0 < 3; s0++)
#pragma unroll
        for (int kw = 0; kw < 3; kw++) acc[s0][kw] = make_float2(0.f, 0.f);

    {   // preamble: row F0-1 into v[0]
        int r0 = F0 - 1;
        bool ok0 = tin && (r0 >= 0);
#pragma unroll
        for (int c = 0; c < 8; c++)
            v[0][c] = ok0 ? xp[(size_t)c * FT + (size_t)r0 * T_] : make_float2(0.f, 0.f);
    }

    // 18 row-iterations = 3 macro x 6 steps; inside the 6-step unroll all
    // ring-slot and buffer indices are compile-time constants.
#pragma unroll 1
    for (int mi = 0; mi < 3; mi++) {
#pragma unroll
        for (int s = 0; s < 6; s++) {
            int rr = mi * 6 + s;
            int r = F0 - 1 + rr;
            int cur = s & 1, nxt = cur ^ 1;

            // prefetch next row into the other buffer
            int rn = r + 1;
            bool okn = tin && (rn < F_) && (rn <= F0 + FSEG);
#pragma unroll
            for (int c = 0; c < 8; c++)
                v[nxt][c] = okn ? xp[(size_t)c * FT + (size_t)rn * T_] : make_float2(0.f, 0.f);

            // accumulate row r: A = row r-1 (kh2), B = row r (kh1), C = row r+1 (kh0)
            accum_row(v[cur], wef, acc[s % 3], acc[(s + 1) % 3], acc[(s + 2) % 3]);

            if (rr >= 2) {
                // output row m = r-1 from slot A = acc[s%3]
                float2 bl, br;
                bl.x = __shfl_up_sync(0xffffffffu, acc[s % 3][0].x, 1);
                bl.y = __shfl_up_sync(0xffffffffu, acc[s % 3][0].y, 1);
                br.x = __shfl_down_sync(0xffffffffu, acc[s % 3][2].x, 1);
                br.y = __shfl_down_sync(0xffffffffu, acc[s % 3][2].y, 1);
                if (tout) {
                    int m = r - 1;
                    float2 wv = make_float2(s_base.x + bl.x + acc[s % 3][1].x + br.x,
                                            s_base.y + bl.y + acc[s % 3][1].y + br.y);
                    // reload row m (L1 hit: fetched 2 iterations ago, default caching)
                    float2 pv[8];
#pragma unroll
                    for (int c = 0; c < 8; c++)
                        pv[c] = xp[(size_t)c * FT + (size_t)m * T_];
#pragma unroll
                    for (int c = 0; c < 8; c++) {
                        float2 g = s_awf[c][m - F0];
                        float2 wt = s_wt[c][t];
                        wv.x = fmaf(g.x * wt.x, pv[c].x, wv.x);
                        wv.y = fmaf(g.y * wt.y, pv[c].y, wv.y);
                    }
                    float sr = sigm(wv.x), si = sigm(wv.y);
#pragma unroll
                    for (int c = 0; c < 8; c++)
                        __stcs(op + (size_t)c * FT + (size_t)m * T_, make_float2(pv[c].x * sr, pv[c].y * si));
                }
            }

            // clear retired slot A — it is reused as slot C two steps later
#pragma unroll
            for (int kw = 0; kw < 3; kw++) acc[s % 3][kw] = make_float2(0.f, 0.f);
        }
    }
}

// ------------------------------- launcher ------------------------------------
extern "C" void kernel_launch(void* const* d_in, const int* in_sizes, int n_in,
                              void* d_out, int out_size) {
    const float2* x    = (const float2*)d_in[0];
    const float* w1r   = (const float*)d_in[1];
    const float* b1r   = (const float*)d_in[2];
    const float* w1i   = (const float*)d_in[3];
    const float* b1i   = (const float*)d_in[4];
    const float* w3r   = (const float*)d_in[5];
    const float* b3r   = (const float*)d_in[6];
    const float* w3i   = (const float*)d_in[7];
    const float* b3i   = (const float*)d_in[8];
    const float* gnw_r = (const float*)d_in[9];
    const float* gnb_r = (const float*)d_in[10];
    const float* gnw_i = (const float*)d_in[11];
    const float* gnb_i = (const float*)d_in[12];
    float2* out = (float2*)d_out;

    k1_rowcol<<<NC * 2, 256>>>(x);
    k2_gates<<<N_, 256>>>(w1r, b1r, w1i, b1i, w3r, b3r, w3i, b3i, gnb_r, gnb_i);
    k3_stats<<<NC, 256>>>(x);
    dim3 g4(F_ / FSEG, N_);
    k4_warp<<<g4, K4_THREADS>>>(x, out, gnw_r, gnb_r, gnw_i, gnb_i);
}